// round 11
// baseline (speedup 1.0000x reference)
#include <cuda_runtime.h>

#define NN 4
#define AA 8732
#define CC 81
#define TPB 256
#define NBLK ((AA + TPB - 1) / TPB)      /* 35: k_post blocks per batch */

#define APB 64                            /* anchors per k_prep block (4 thr/anchor) */
#define NBLK2 ((AA + APB - 1) / APB)      /* 137 */

#define TPI 256                           /* k_iou threads */
#define JSPLIT 35                         /* 35*256 = 8960 >= 8732 */

// ---------------- scratch (device globals: allocation-free) ----------------
__device__ float4 g_pbox[NN * AA];    // (l, t, r, b)
__device__ float4 g_gbox[NN * AA];
__device__ float  g_parea[NN * AA];
__device__ float  g_garea[NN * AA];
__device__ float  g_validf[NN * AA];
__device__ float  g_con[NN * AA];
__device__ float  g_conneg[NN * AA];
__device__ float  g_sl1[NN * AA];
__device__ float  g_ioup[JSPLIT][NN * AA];  // partial IoU sums (positives only)
__device__ int    g_plist[NN * AA];   // compacted positive anchor ids
__device__ int    g_cnt[NN];          // zero-init; reset by k_post each run
__device__ int    g_pos[NN];
__device__ unsigned g_thr[NN];
__device__ float  g_part1[NN * NBLK];
__device__ float  g_part2[NN * NBLK];
__device__ int    g_done;             // zero-init; reset by k_post each run

// -------- K1: per-anchor prep; 4-way class-split softmax + compaction ------
__global__ void __launch_bounds__(TPB) k_prep(
    const float* __restrict__ ploc, const float* __restrict__ plabel,
    const float* __restrict__ gloc, const int* __restrict__ glabel,
    const float* __restrict__ dbox)
{
    int n = blockIdx.y;
    int la = threadIdx.x & (APB - 1);
    int q = threadIdx.x >> 6;             // 0..3
    int a = blockIdx.x * APB + la;
    bool act = (a < AA);

    __shared__ float s_se[TPB];
    __shared__ float s_xg[APB];

    int lab = 0;
    float se0 = 0.f, se1 = 0.f;
    if (act) {
        lab = glabel[n * AA + a];
        const float* pp = plabel + (size_t)n * CC * AA + a;
        int c0 = (q == 0) ? 0 : (20 * q + 1);
        int c1 = 20 * q + 21;
        #pragma unroll 2
        for (int c = c0; c + 1 < c1; c += 2) {
            se0 += __expf(pp[(size_t)c * AA]);
            se1 += __expf(pp[(size_t)(c + 1) * AA]);
        }
        if ((c1 - c0) & 1) se0 += __expf(pp[(size_t)(c1 - 1) * AA]);
        if (lab >= c0 && lab < c1) s_xg[la] = pp[(size_t)lab * AA];
    }
    s_se[threadIdx.x] = se0 + se1;
    __syncthreads();

    if (act && q == 0) {
        float con = __logf(((s_se[la] + s_se[la + APB]) +
                            (s_se[la + 2 * APB] + s_se[la + 3 * APB]))) - s_xg[la];

        float dx = dbox[0 * AA + a], dy = dbox[1 * AA + a];
        float dw = dbox[2 * AA + a], dh = dbox[3 * AA + a];
        const float* pl = ploc + (size_t)n * 4 * AA;
        const float* gg = gloc + (size_t)n * 4 * AA;
        float px = pl[a], py = pl[AA + a], pw = pl[2 * AA + a], ph = pl[3 * AA + a];
        float gx = gg[a], gy = gg[AA + a], gw = gg[2 * AA + a], gh = gg[3 * AA + a];

        // encode targets (vec_gd) + smooth L1
        float gxt = 10.0f * (gx - dx) / dw;
        float gyt = 10.0f * (gy - dy) / dh;
        float gwt = 5.0f * __logf(gw / dw);
        float ght = 5.0f * __logf(gh / dh);

        float s = 0.f, d, ad;
        d = px - gxt; ad = fabsf(d); s += (ad < 1.f) ? 0.5f * d * d : ad - 0.5f;
        d = py - gyt; ad = fabsf(d); s += (ad < 1.f) ? 0.5f * d * d : ad - 0.5f;
        d = pw - gwt; ad = fabsf(d); s += (ad < 1.f) ? 0.5f * d * d : ad - 0.5f;
        d = ph - ght; ad = fabsf(d); s += (ad < 1.f) ? 0.5f * d * d : ad - 0.5f;

        // decode p -> ltrb
        float pcx = 0.1f * px * dw + dx, pcy = 0.1f * py * dh + dy;
        float pww = __expf(0.2f * pw) * dw, phh = __expf(0.2f * ph) * dh;
        float plx = pcx - 0.5f * pww, pty = pcy - 0.5f * phh;
        float prx = pcx + 0.5f * pww, pby = pcy + 0.5f * phh;
        // decode g -> ltrb
        float gcx = 0.1f * gx * dw + dx, gcy = 0.1f * gy * dh + dy;
        float gww = __expf(0.2f * gw) * dw, ghh = __expf(0.2f * gh) * dh;
        float glx = gcx - 0.5f * gww, gty = gcy - 0.5f * ghh;
        float grx = gcx + 0.5f * gww, gby = gcy + 0.5f * ghh;

        float pa = (prx - plx) * (pby - pty);
        float ga = (grx - glx) * (gby - gty);
        int valid = (plx < prx) && (pty < pby);

        int id = n * AA + a;
        g_pbox[id] = make_float4(plx, pty, prx, pby);
        g_gbox[id] = make_float4(glx, gty, grx, gby);
        g_parea[id] = pa;
        g_garea[id] = ga;
        g_validf[id] = valid ? 1.f : 0.f;
        g_con[id] = con;
        g_conneg[id] = (lab > 0) ? 0.f : con;
        g_sl1[id] = s;

        if (lab > 0) {
            int idx = atomicAdd(&g_cnt[n], 1);
            g_plist[n * AA + idx] = a;
        }
    }
}

// ------- K2: j-split IoU partials (positives in threads) + radix select ----
// grid (JSPLIT+1, NN). bx==JSPLIT: exact K-th largest of conneg bits.
// bx<JSPLIT: load 256-g-box tile to shared once; each thread sweeps its
// positive anchor(s) over the tile; partial to g_ioup[bx][anchor].
__global__ void __launch_bounds__(TPI) k_iou()
{
    int n = blockIdx.y;
    int bx = blockIdx.x;
    int t = threadIdx.x;

    if (bx == JSPLIT) {
        // ---- radix select on float bits of conneg ----
        __shared__ int s_hist[256];
        __shared__ int s_suf[256];
        __shared__ unsigned s_prefix;
        __shared__ int s_rem;
        int pos = g_cnt[n];
        int K = min(3 * pos, AA);
        if (t == 0) { g_pos[n] = pos; s_prefix = 0; s_rem = K; }
        __syncthreads();
        if (K <= 0) { if (t == 0) g_thr[n] = 0xFFFFFFFFu; return; }

        for (int pass = 0; pass < 4; pass++) {
            int shift = 24 - 8 * pass;
            s_hist[t] = 0;
            __syncthreads();
            unsigned pref = s_prefix;
            int rem = s_rem;
            for (int i = t; i < 9216; i += TPI) {
                bool ok = (i < AA);
                unsigned bits = 0;
                if (ok) {
                    bits = __float_as_uint(g_conneg[n * AA + i]);
                    if (pass > 0 && (bits >> (shift + 8)) != pref) ok = false;
                }
                int bin = ok ? (int)((bits >> shift) & 0xFF) : (256 + (t & 31));
                unsigned mm = __match_any_sync(0xffffffffu, bin);
                if (ok && (t & 31) == (__ffs(mm) - 1)) atomicAdd(&s_hist[bin], __popc(mm));
            }
            __syncthreads();
            s_suf[t] = s_hist[t];
            __syncthreads();
            for (int st = 1; st < 256; st <<= 1) {
                int v = s_suf[t] + ((t + st < 256) ? s_suf[t + st] : 0);
                __syncthreads();
                s_suf[t] = v;
                __syncthreads();
            }
            int gt = (t < 255) ? s_suf[t + 1] : 0;
            if (s_suf[t] >= rem && gt < rem) {
                s_prefix = (pref << 8) | (unsigned)t;
                s_rem = rem - gt;
            }
            __syncthreads();
        }
        if (t == 0) g_thr[n] = s_prefix;
        return;
    }

    __shared__ float4 sb[TPI];
    __shared__ float  sa[TPI];

    int j = bx * TPI + t;
    if (j < AA) {
        sb[t] = g_gbox[n * AA + j];
        sa[t] = g_garea[n * AA + j];
    } else {
        sb[t] = make_float4(1e30f, 1e30f, 1e30f, 1e30f);
        sa[t] = 1.0f;
    }
    __syncthreads();

    int cnt = g_cnt[n];
    for (int slot = t; slot < cnt; slot += TPI) {
        int i = g_plist[n * AA + slot];
        float4 pb = g_pbox[n * AA + i];
        float pa = g_parea[n * AA + i];

        float acc0 = 0.f, acc1 = 0.f, acc2 = 0.f, acc3 = 0.f;
        #pragma unroll 8
        for (int u = 0; u < TPI; u++) {
            float4 gb = sb[u];
            float ga = sa[u];
            float x1 = fmaxf(pb.x, gb.x);
            float x2 = fminf(pb.z, gb.z);
            float y1 = fmaxf(pb.y, gb.y);
            float y2 = fminf(pb.w, gb.w);
            float iw = fmaxf(x2 - x1, 0.f);
            float ih = fmaxf(y2 - y1, 0.f);
            float inter = iw * ih;
            float ua = fmaf(inter, -1.0f, pa + ga);
            float r;
            asm("rcp.approx.f32 %0, %1;" : "=f"(r) : "f"(ua));
            float v = inter * r;
            switch (u & 3) {
                case 0: acc0 += v; break;
                case 1: acc1 += v; break;
                case 2: acc2 += v; break;
                default: acc3 += v; break;
            }
        }
        g_ioup[bx][n * AA + i] = (acc0 + acc1) + (acc2 + acc3);
    }
}

// ------- K3: epilogue + block reduce + last-block deterministic final ------
__global__ void __launch_bounds__(TPB) k_post(const int* __restrict__ glabel,
                                              float* __restrict__ out)
{
    int n = blockIdx.y;
    int i = blockIdx.x * TPB + threadIdx.x;
    int t = threadIdx.x;

    float a1 = 0.f, a2 = 0.f;
    if (i < AA) {
        int id = n * AA + i;
        float con = g_con[id];
        float cn = g_conneg[id];
        int lab = glabel[id];

        if (lab > 0) {
            float iou = 0.f;
            #pragma unroll
            for (int s = 0; s < JSPLIT; s++) iou += g_ioup[s][id];
            float sl1 = g_sl1[id];
            float vld = g_validf[id];
            float w = (vld != 0.f) ? 0.01f * iou : 0.f;
            a1 = sl1 / (sl1 + w) * sl1;
        }
        float nm = (__float_as_uint(cn) >= g_thr[n]) ? 1.f : 0.f;
        float mm = (lab > 0) ? 1.f : 0.f;
        a2 = con * (mm + nm);
    }

    __shared__ float r1[TPB];
    __shared__ float r2[TPB];
    r1[t] = a1; r2[t] = a2;
    __syncthreads();
    for (int sdim = TPB / 2; sdim > 0; sdim >>= 1) {
        if (t < sdim) { r1[t] += r1[t + sdim]; r2[t] += r2[t + sdim]; }
        __syncthreads();
    }

    __shared__ int s_last;
    if (t == 0) {
        g_part1[n * NBLK + blockIdx.x] = r1[0];
        g_part2[n * NBLK + blockIdx.x] = r2[0];
        __threadfence();
        int prev = atomicAdd(&g_done, 1);
        s_last = (prev == NN * NBLK - 1) ? 1 : 0;
    }
    __syncthreads();

    if (s_last) {
        __shared__ float s_val[NN];
        int w = t >> 5, lane = t & 31;
        if (w < NN) {
            float s1 = 0.f, s2 = 0.f;
            for (int b = lane; b < NBLK; b += 32) {
                s1 += g_part1[w * NBLK + b];
                s2 += g_part2[w * NBLK + b];
            }
            float v = s1 + s2;
            #pragma unroll
            for (int o = 16; o > 0; o >>= 1) v += __shfl_down_sync(0xffffffffu, v, o);
            if (lane == 0) {
                int pos = g_pos[w];
                s_val[w] = (pos > 0) ? v / fmaxf((float)pos, 1e-6f) : 0.f;
            }
        }
        __syncthreads();
        if (t == 0) {
            out[0] = (s_val[0] + s_val[1] + s_val[2] + s_val[3]) * 0.25f;
            g_done = 0;                       // reset for next graph replay
            #pragma unroll
            for (int nn = 0; nn < NN; nn++) g_cnt[nn] = 0;
        }
    }
}

// ---------------- launch ----------------
extern "C" void kernel_launch(void* const* d_in, const int* in_sizes, int n_in,
                              void* d_out, int out_size)
{
    const float* ploc   = (const float*)d_in[0];
    const float* plabel = (const float*)d_in[1];
    const float* gloc   = (const float*)d_in[2];
    const int*   glabel = (const int*)d_in[3];
    const float* dbox   = (const float*)d_in[4];
    float* out = (float*)d_out;

    k_prep<<<dim3(NBLK2, NN), TPB>>>(ploc, plabel, gloc, glabel, dbox);
    k_iou<<<dim3(JSPLIT + 1, NN), TPI>>>();
    k_post<<<dim3(NBLK, NN), TPB>>>(glabel, out);
}

// round 12
// speedup vs baseline: 1.1660x; 1.1660x over previous
#include <cuda_runtime.h>

#define NN 4
#define AA 8732
#define CC 81
#define TPB 256
#define NBLK ((AA + TPB - 1) / TPB)      /* 35: k_post blocks per batch */

#define APB 128                           /* anchors per k_prep block (2 thr/anchor) */
#define NBLK2 ((AA + APB - 1) / APB)      /* 69 */

#define TPI 256                           /* k_iou threads */
#define NA 8                              /* anchors per k_iou block */
#define NGRP 64                           /* anchor-group blocks per batch */
#define NU 36                             /* 36*256 = 9216 >= 8732 */

// ---------------- scratch (device globals: allocation-free) ----------------
__device__ float4 g_pbox[NN * AA];    // (l, t, r, b)
__device__ float4 g_gbox[NN * AA];
__device__ float  g_parea[NN * AA];
__device__ float  g_garea[NN * AA];
__device__ float  g_validf[NN * AA];
__device__ float  g_con[NN * AA];
__device__ float  g_conneg[NN * AA];
__device__ float  g_sl1[NN * AA];
__device__ float  g_iou[NN * AA];     // written only for positive anchors
__device__ int    g_plist[NN * AA];   // compacted positive anchor ids
__device__ int    g_cnt[NN];          // zero-init; reset by k_post each run
__device__ int    g_pos[NN];
__device__ unsigned g_thr[NN];
__device__ float  g_part1[NN * NBLK];
__device__ float  g_part2[NN * NBLK];
__device__ int    g_done;             // zero-init; reset by k_post each run

// ---------------- K1: per-anchor prep, class-split softmax + compaction ----
__global__ void __launch_bounds__(TPB) k_prep(
    const float* __restrict__ ploc, const float* __restrict__ plabel,
    const float* __restrict__ gloc, const int* __restrict__ glabel,
    const float* __restrict__ dbox)
{
    int n = blockIdx.y;
    int la = threadIdx.x & (APB - 1);
    int half = threadIdx.x >> 7;          // 0 or 1
    int a = blockIdx.x * APB + la;
    bool act = (a < AA);

    __shared__ float s_se[TPB];
    __shared__ float s_xg[APB];

    int lab = 0;
    float se = 0.f;
    if (act) {
        lab = glabel[n * AA + a];
        const float* pp = plabel + (size_t)n * CC * AA + a;
        int c0 = half ? 41 : 0;
        int c1 = half ? CC : 41;
        #pragma unroll 8
        for (int c = c0; c < c1; c++) se += __expf(pp[(size_t)c * AA]);
        if ((lab >= 41) == (half == 1)) s_xg[la] = pp[(size_t)lab * AA];
    }
    s_se[threadIdx.x] = se;
    __syncthreads();

    if (act && half == 0) {
        float con = __logf(s_se[la] + s_se[la + APB]) - s_xg[la];

        float dx = dbox[0 * AA + a], dy = dbox[1 * AA + a];
        float dw = dbox[2 * AA + a], dh = dbox[3 * AA + a];
        const float* pl = ploc + (size_t)n * 4 * AA;
        const float* gg = gloc + (size_t)n * 4 * AA;
        float px = pl[a], py = pl[AA + a], pw = pl[2 * AA + a], ph = pl[3 * AA + a];
        float gx = gg[a], gy = gg[AA + a], gw = gg[2 * AA + a], gh = gg[3 * AA + a];

        // encode targets (vec_gd) + smooth L1
        float gxt = 10.0f * (gx - dx) / dw;
        float gyt = 10.0f * (gy - dy) / dh;
        float gwt = 5.0f * __logf(gw / dw);
        float ght = 5.0f * __logf(gh / dh);

        float s = 0.f, d, ad;
        d = px - gxt; ad = fabsf(d); s += (ad < 1.f) ? 0.5f * d * d : ad - 0.5f;
        d = py - gyt; ad = fabsf(d); s += (ad < 1.f) ? 0.5f * d * d : ad - 0.5f;
        d = pw - gwt; ad = fabsf(d); s += (ad < 1.f) ? 0.5f * d * d : ad - 0.5f;
        d = ph - ght; ad = fabsf(d); s += (ad < 1.f) ? 0.5f * d * d : ad - 0.5f;

        // decode p -> ltrb
        float pcx = 0.1f * px * dw + dx, pcy = 0.1f * py * dh + dy;
        float pww = __expf(0.2f * pw) * dw, phh = __expf(0.2f * ph) * dh;
        float plx = pcx - 0.5f * pww, pty = pcy - 0.5f * phh;
        float prx = pcx + 0.5f * pww, pby = pcy + 0.5f * phh;
        // decode g -> ltrb
        float gcx = 0.1f * gx * dw + dx, gcy = 0.1f * gy * dh + dy;
        float gww = __expf(0.2f * gw) * dw, ghh = __expf(0.2f * gh) * dh;
        float glx = gcx - 0.5f * gww, gty = gcy - 0.5f * ghh;
        float grx = gcx + 0.5f * gww, gby = gcy + 0.5f * gh * 0.f + gcy + 0.5f * ghh - gcy; // see below

        // (avoid accidental refactor: recompute cleanly)
        gby = gcy + 0.5f * ghh;

        float pa = (prx - plx) * (pby - pty);
        float ga = (grx - glx) * (gby - gty);
        int valid = (plx < prx) && (pty < pby);

        int id = n * AA + a;
        g_pbox[id] = make_float4(plx, pty, prx, pby);
        g_gbox[id] = make_float4(glx, gty, grx, gby);
        g_parea[id] = pa;
        g_garea[id] = ga;
        g_validf[id] = valid ? 1.f : 0.f;
        g_con[id] = con;
        g_conneg[id] = (lab > 0) ? 0.f : con;
        g_sl1[id] = s;

        if (lab > 0) {
            int idx = atomicAdd(&g_cnt[n], 1);
            g_plist[n * AA + idx] = a;
        }
    }
}

// ------- K2: grouped IoU sums (8 anchors/block) + reg-cached radix select --
// grid (NGRP+1, NN). bx==NGRP: exact K-th largest of conneg bits (values
// cached in registers; 4 passes, no global rescans). bx<NGRP: stream all
// g-boxes once per 8-anchor group; 8 independent IoU chains per thread.
__global__ void __launch_bounds__(TPI) k_iou()
{
    int n = blockIdx.y;
    int bx = blockIdx.x;
    int t = threadIdx.x;

    if (bx == NGRP) {
        __shared__ int s_hist[256];
        __shared__ int s_suf[256];
        __shared__ unsigned s_prefix;
        __shared__ int s_rem;
        int pos = g_cnt[n];
        int K = min(3 * pos, AA);
        if (t == 0) { g_pos[n] = pos; s_prefix = 0; s_rem = K; }
        __syncthreads();
        if (K <= 0) { if (t == 0) g_thr[n] = 0xFFFFFFFFu; return; }

        // cache all values in registers (36 per thread)
        unsigned vals[NU];
        #pragma unroll
        for (int u = 0; u < NU; u++) {
            int i = u * TPI + t;
            vals[u] = (i < AA) ? __float_as_uint(g_conneg[n * AA + i]) : 0u;
        }

        for (int pass = 0; pass < 4; pass++) {
            int shift = 24 - 8 * pass;
            s_hist[t] = 0;
            __syncthreads();
            unsigned pref = s_prefix;
            int rem = s_rem;
            #pragma unroll
            for (int u = 0; u < NU; u++) {
                unsigned b = vals[u];
                bool ok = (pass == 0) || ((b >> (shift + 8)) == pref);
                int bin = ok ? (int)((b >> shift) & 0xFF) : (256 + (t & 31));
                unsigned mm = __match_any_sync(0xffffffffu, bin);
                if (ok && (t & 31) == (__ffs(mm) - 1)) atomicAdd(&s_hist[bin], __popc(mm));
            }
            __syncthreads();
            s_suf[t] = s_hist[t];
            __syncthreads();
            for (int st = 1; st < 256; st <<= 1) {
                int v = s_suf[t] + ((t + st < 256) ? s_suf[t + st] : 0);
                __syncthreads();
                s_suf[t] = v;
                __syncthreads();
            }
            int gt = (t < 255) ? s_suf[t + 1] : 0;
            if (s_suf[t] >= rem && gt < rem) {
                s_prefix = (pref << 8) | (unsigned)t;
                s_rem = rem - gt;
            }
            __syncthreads();
        }
        if (t == 0) g_thr[n] = s_prefix;
        return;
    }

    int cnt = g_cnt[n];
    __shared__ float  s_anch[NA * 5];     // l, t, r, b, area per anchor
    __shared__ int    s_aid[NA];
    __shared__ float  s_part[8][NA];      // per-warp partials

    for (int base = bx * NA; base < cnt; base += NGRP * NA) {
        if (t < NA) {
            int slot = base + t;
            int aid = (slot < cnt) ? g_plist[n * AA + slot] : -1;
            s_aid[t] = aid;
            if (aid >= 0) {
                float4 pbv = g_pbox[n * AA + aid];
                s_anch[t * 5 + 0] = pbv.x;
                s_anch[t * 5 + 1] = pbv.y;
                s_anch[t * 5 + 2] = pbv.z;
                s_anch[t * 5 + 3] = pbv.w;
                s_anch[t * 5 + 4] = g_parea[n * AA + aid];
            } else {
                s_anch[t * 5 + 0] = -2e30f;
                s_anch[t * 5 + 1] = -2e30f;
                s_anch[t * 5 + 2] = -2e30f;
                s_anch[t * 5 + 3] = -2e30f;
                s_anch[t * 5 + 4] = 1.0f;
            }
        }
        __syncthreads();

        float al[NA], atp[NA], ar[NA], ab[NA], aar[NA], acc[NA];
        #pragma unroll
        for (int k = 0; k < NA; k++) {
            al[k]  = s_anch[k * 5 + 0];
            atp[k] = s_anch[k * 5 + 1];
            ar[k]  = s_anch[k * 5 + 2];
            ab[k]  = s_anch[k * 5 + 3];
            aar[k] = s_anch[k * 5 + 4];
            acc[k] = 0.f;
        }

        #pragma unroll 4
        for (int u = 0; u < 35; u++) {        // 35*256 = 8960 >= 8732
            int j = u * TPI + t;
            float4 gb;
            float ga;
            if (j < AA) {
                gb = g_gbox[n * AA + j];
                ga = g_garea[n * AA + j];
            } else {
                gb = make_float4(1e30f, 1e30f, 1e30f, 1e30f);
                ga = 1.0f;
            }
            #pragma unroll
            for (int k = 0; k < NA; k++) {
                float x1 = fmaxf(al[k], gb.x);
                float x2 = fminf(ar[k], gb.z);
                float y1 = fmaxf(atp[k], gb.y);
                float y2 = fminf(ab[k], gb.w);
                float iw = fmaxf(x2 - x1, 0.f);
                float ih = fmaxf(y2 - y1, 0.f);
                float inter = iw * ih;
                float ua = fmaf(inter, -1.0f, aar[k] + ga);
                float r;
                asm("rcp.approx.f32 %0, %1;" : "=f"(r) : "f"(ua));
                acc[k] = fmaf(inter, r, acc[k]);
            }
        }

        int w = t >> 5, lane = t & 31;
        #pragma unroll
        for (int k = 0; k < NA; k++) {
            float v = acc[k];
            #pragma unroll
            for (int o = 16; o > 0; o >>= 1) v += __shfl_down_sync(0xffffffffu, v, o);
            if (lane == 0) s_part[w][k] = v;
        }
        __syncthreads();
        if (t < NA) {
            int aid = s_aid[t];
            if (aid >= 0) {
                float sum = 0.f;
                #pragma unroll
                for (int w2 = 0; w2 < 8; w2++) sum += s_part[w2][t];
                g_iou[n * AA + aid] = sum;
            }
        }
        __syncthreads();
    }
}

// ------- K3: epilogue + block reduce + last-block deterministic final ------
__global__ void __launch_bounds__(TPB) k_post(const int* __restrict__ glabel,
                                              float* __restrict__ out)
{
    int n = blockIdx.y;
    int i = blockIdx.x * TPB + threadIdx.x;
    int t = threadIdx.x;

    float a1 = 0.f, a2 = 0.f;
    if (i < AA) {
        int id = n * AA + i;
        float con = g_con[id];
        float cn = g_conneg[id];
        int lab = glabel[id];

        if (lab > 0) {
            float sl1 = g_sl1[id];
            float vld = g_validf[id];
            float iou = g_iou[id];
            float w = (vld != 0.f) ? 0.01f * iou : 0.f;
            a1 = sl1 / (sl1 + w) * sl1;
        }
        float nm = (__float_as_uint(cn) >= g_thr[n]) ? 1.f : 0.f;
        float mm = (lab > 0) ? 1.f : 0.f;
        a2 = con * (mm + nm);
    }

    __shared__ float r1[TPB];
    __shared__ float r2[TPB];
    r1[t] = a1; r2[t] = a2;
    __syncthreads();
    for (int sdim = TPB / 2; sdim > 0; sdim >>= 1) {
        if (t < sdim) { r1[t] += r1[t + sdim]; r2[t] += r2[t + sdim]; }
        __syncthreads();
    }

    __shared__ int s_last;
    if (t == 0) {
        g_part1[n * NBLK + blockIdx.x] = r1[0];
        g_part2[n * NBLK + blockIdx.x] = r2[0];
        __threadfence();
        int prev = atomicAdd(&g_done, 1);
        s_last = (prev == NN * NBLK - 1) ? 1 : 0;
    }
    __syncthreads();

    if (s_last) {
        __shared__ float s_val[NN];
        int w = t >> 5, lane = t & 31;
        if (w < NN) {
            float s1 = 0.f, s2 = 0.f;
            for (int b = lane; b < NBLK; b += 32) {
                s1 += g_part1[w * NBLK + b];
                s2 += g_part2[w * NBLK + b];
            }
            float v = s1 + s2;
            #pragma unroll
            for (int o = 16; o > 0; o >>= 1) v += __shfl_down_sync(0xffffffffu, v, o);
            if (lane == 0) {
                int pos = g_pos[w];
                s_val[w] = (pos > 0) ? v / fmaxf((float)pos, 1e-6f) : 0.f;
            }
        }
        __syncthreads();
        if (t == 0) {
            out[0] = (s_val[0] + s_val[1] + s_val[2] + s_val[3]) * 0.25f;
            g_done = 0;                       // reset for next graph replay
            #pragma unroll
            for (int nn = 0; nn < NN; nn++) g_cnt[nn] = 0;
        }
    }
}

// ---------------- launch ----------------
extern "C" void kernel_launch(void* const* d_in, const int* in_sizes, int n_in,
                              void* d_out, int out_size)
{
    const float* ploc   = (const float*)d_in[0];
    const float* plabel = (const float*)d_in[1];
    const float* gloc   = (const float*)d_in[2];
    const int*   glabel = (const int*)d_in[3];
    const float* dbox   = (const float*)d_in[4];
    float* out = (float*)d_out;

    k_prep<<<dim3(NBLK2, NN), TPB>>>(ploc, plabel, gloc, glabel, dbox);
    k_iou<<<dim3(NGRP + 1, NN), TPI>>>();
    k_post<<<dim3(NBLK, NN), TPB>>>(glabel, out);
}

// round 14
// speedup vs baseline: 1.1891x; 1.0198x over previous
#include <cuda_runtime.h>

#define NN 4
#define AA 8732
#define CC 81
#define TPB 256
#define NBLK 35                 /* post units per batch (35*256 >= 8732) */
#define APB 128                 /* anchors per prep unit (2 thr/anchor) */
#define NBLK2 69                /* prep units per batch */
#define G (NBLK2 * NN)          /* 276 blocks; <=296 (2/SM) -> all resident */
#define NPAIR 256               /* slot-pairs per batch (covers 512 slots) */
#define NIU (NPAIR * NN)        /* 1024 iou units */
#define NUNITS (NIU + NN)       /* + 4 select units */

// ---------------- scratch (device globals: allocation-free) ----------------
__device__ float4 g_pbox[NN * AA];
__device__ float4 g_gbox[NN * AA];
__device__ float  g_parea[NN * AA];
__device__ float  g_garea[NN * AA];
__device__ float  g_validf[NN * AA];
__device__ float  g_con[NN * AA];
__device__ float  g_conneg[NN * AA];
__device__ float  g_sl1[NN * AA];
__device__ float  g_iou[NN * AA];
__device__ int    g_plist[NN * AA];
__device__ int    g_cnt[NN];        // zero-init; reset by last block
__device__ int    g_pos[NN];
__device__ unsigned g_thr[NN];
__device__ float  g_part1[NN * NBLK];
__device__ float  g_part2[NN * NBLK];
__device__ int    g_bar1, g_bar2, g_done;   // zero-init; reset by last block

__global__ void __launch_bounds__(TPB, 2) k_all(
    const float* __restrict__ ploc, const float* __restrict__ plabel,
    const float* __restrict__ gloc, const int* __restrict__ glabel,
    const float* __restrict__ dbox, float* __restrict__ out)
{
    int bx = blockIdx.x;
    int t  = threadIdx.x;

    __shared__ float s_se[TPB];
    __shared__ float s_xg[APB];
    __shared__ int   s_hist[256];
    __shared__ int   s_suf[256];
    __shared__ unsigned s_prefix;
    __shared__ int   s_rem;
    __shared__ float s_red0[TPB];
    __shared__ float s_red1[TPB];
    __shared__ float s_val[NN];
    __shared__ int   s_last;

    // ================= Phase A: per-anchor prep (1 unit per block) ========
    {
        int n   = bx / NBLK2;
        int blk = bx % NBLK2;
        int la = t & (APB - 1);
        int half = t >> 7;                 // 0 or 1
        int a = blk * APB + la;
        bool act = (a < AA);

        int lab = 0;
        float se = 0.f;
        if (act) {
            lab = glabel[n * AA + a];
            const float* pp = plabel + (size_t)n * CC * AA + a;
            int c0 = half ? 41 : 0;
            int c1 = half ? CC : 41;
            #pragma unroll 8
            for (int c = c0; c < c1; c++) se += __expf(pp[(size_t)c * AA]);
            if ((lab >= 41) == (half == 1)) s_xg[la] = pp[(size_t)lab * AA];
        }
        s_se[t] = se;
        __syncthreads();

        if (act && half == 0) {
            float con = __logf(s_se[la] + s_se[la + APB]) - s_xg[la];

            float dx = dbox[0 * AA + a], dy = dbox[1 * AA + a];
            float dw = dbox[2 * AA + a], dh = dbox[3 * AA + a];
            const float* pl = ploc + (size_t)n * 4 * AA;
            const float* gg = gloc + (size_t)n * 4 * AA;
            float px = pl[a], py = pl[AA + a], pw = pl[2 * AA + a], ph = pl[3 * AA + a];
            float gx = gg[a], gy = gg[AA + a], gw = gg[2 * AA + a], gh = gg[3 * AA + a];

            float gxt = 10.0f * (gx - dx) / dw;
            float gyt = 10.0f * (gy - dy) / dh;
            float gwt = 5.0f * __logf(gw / dw);
            float ght = 5.0f * __logf(gh / dh);

            float s = 0.f, d, ad;
            d = px - gxt; ad = fabsf(d); s += (ad < 1.f) ? 0.5f * d * d : ad - 0.5f;
            d = py - gyt; ad = fabsf(d); s += (ad < 1.f) ? 0.5f * d * d : ad - 0.5f;
            d = pw - gwt; ad = fabsf(d); s += (ad < 1.f) ? 0.5f * d * d : ad - 0.5f;
            d = ph - ght; ad = fabsf(d); s += (ad < 1.f) ? 0.5f * d * d : ad - 0.5f;

            float pcx = 0.1f * px * dw + dx, pcy = 0.1f * py * dh + dy;
            float pww = __expf(0.2f * pw) * dw, phh = __expf(0.2f * ph) * dh;
            float plx = pcx - 0.5f * pww, pty = pcy - 0.5f * phh;
            float prx = pcx + 0.5f * pww, pby = pcy + 0.5f * phh;
            float gcx = 0.1f * gx * dw + dx, gcy = 0.1f * gy * dh + dy;
            float gww = __expf(0.2f * gw) * dw, ghh = __expf(0.2f * gh) * dh;
            float glx = gcx - 0.5f * gww, gty = gcy - 0.5f * ghh;
            float grx = gcx + 0.5f * gww, gby = gcy + 0.5f * ghh;

            float pa = (prx - plx) * (pby - pty);
            float ga = (grx - glx) * (gby - gty);
            int valid = (plx < prx) && (pty < pby);

            int id = n * AA + a;
            g_pbox[id] = make_float4(plx, pty, prx, pby);
            g_gbox[id] = make_float4(glx, gty, grx, gby);
            g_parea[id] = pa;
            g_garea[id] = ga;
            g_validf[id] = valid ? 1.f : 0.f;
            g_con[id] = con;
            g_conneg[id] = (lab > 0) ? 0.f : con;
            g_sl1[id] = s;

            if (lab > 0) {
                int idx = atomicAdd(&g_cnt[n], 1);
                g_plist[n * AA + idx] = a;
            }
        }
    }

    // ---- grid barrier 1 ----
    __syncthreads();
    __threadfence();
    if (t == 0) {
        atomicAdd(&g_bar1, 1);
        while (atomicAdd(&g_bar1, 0) < G) __nanosleep(200);
    }
    __syncthreads();

    // ================= Phase B: IoU pair-units + radix select ==============
    for (int u = bx; u < NUNITS; u += G) {
        if (u < NIU) {
            int n = u & 3;
            int pair = u >> 2;
            int cnt = __ldcg(&g_cnt[n]);
            int s0 = pair * 2;
            if (s0 >= cnt) continue;

            int i0 = g_plist[n * AA + s0];
            bool has1 = (s0 + 1 < cnt);
            int i1 = has1 ? g_plist[n * AA + s0 + 1] : 0;

            float4 pb0 = g_pbox[n * AA + i0];
            float  pa0 = g_parea[n * AA + i0];
            float4 pb1;
            float  pa1;
            if (has1) { pb1 = g_pbox[n * AA + i1]; pa1 = g_parea[n * AA + i1]; }
            else { pb1 = make_float4(-2e30f, -2e30f, -2e30f, -2e30f); pa1 = 1.0f; }

            float a0[4] = {0.f, 0.f, 0.f, 0.f};
            float a1[4] = {0.f, 0.f, 0.f, 0.f};
            #pragma unroll 4
            for (int u2 = 0; u2 < 35; u2++) {
                int j = t + u2 * TPB;
                if (j < AA) {
                    float4 gb = g_gbox[n * AA + j];
                    float  ga = g_garea[n * AA + j];
                    {
                        float x1 = fmaxf(pb0.x, gb.x);
                        float x2 = fminf(pb0.z, gb.z);
                        float y1 = fmaxf(pb0.y, gb.y);
                        float y2 = fminf(pb0.w, gb.w);
                        float iw = fmaxf(x2 - x1, 0.f);
                        float ih = fmaxf(y2 - y1, 0.f);
                        float inter = iw * ih;
                        float ua = fmaf(inter, -1.0f, pa0 + ga);
                        float r;
                        asm("rcp.approx.f32 %0, %1;" : "=f"(r) : "f"(ua));
                        a0[u2 & 3] = fmaf(inter, r, a0[u2 & 3]);
                    }
                    {
                        float x1 = fmaxf(pb1.x, gb.x);
                        float x2 = fminf(pb1.z, gb.z);
                        float y1 = fmaxf(pb1.y, gb.y);
                        float y2 = fminf(pb1.w, gb.w);
                        float iw = fmaxf(x2 - x1, 0.f);
                        float ih = fmaxf(y2 - y1, 0.f);
                        float inter = iw * ih;
                        float ua = fmaf(inter, -1.0f, pa1 + ga);
                        float r;
                        asm("rcp.approx.f32 %0, %1;" : "=f"(r) : "f"(ua));
                        a1[u2 & 3] = fmaf(inter, r, a1[u2 & 3]);
                    }
                }
            }
            s_red0[t] = (a0[0] + a0[1]) + (a0[2] + a0[3]);
            s_red1[t] = (a1[0] + a1[1]) + (a1[2] + a1[3]);
            __syncthreads();
            for (int sd = TPB / 2; sd > 0; sd >>= 1) {
                if (t < sd) { s_red0[t] += s_red0[t + sd]; s_red1[t] += s_red1[t + sd]; }
                __syncthreads();
            }
            if (t == 0) {
                g_iou[n * AA + i0] = s_red0[0];
                if (has1) g_iou[n * AA + i1] = s_red1[0];
            }
            __syncthreads();
        } else {
            // ---- radix select: exact K-th largest of conneg bits ----
            int n = u - NIU;
            int pos = __ldcg(&g_cnt[n]);
            int K = min(3 * pos, AA);
            if (t == 0) { g_pos[n] = pos; s_prefix = 0; s_rem = K; }
            __syncthreads();
            if (K <= 0) { if (t == 0) g_thr[n] = 0xFFFFFFFFu; continue; }

            for (int pass = 0; pass < 4; pass++) {
                int shift = 24 - 8 * pass;
                s_hist[t] = 0;
                __syncthreads();
                unsigned pref = s_prefix;
                int rem = s_rem;
                for (int i = t; i < 9216; i += TPB) {
                    bool ok = (i < AA);
                    unsigned bits = 0;
                    if (ok) {
                        bits = __float_as_uint(g_conneg[n * AA + i]);
                        if (pass > 0 && (bits >> (shift + 8)) != pref) ok = false;
                    }
                    int bin = ok ? (int)((bits >> shift) & 0xFF) : (256 + (t & 31));
                    unsigned mm = __match_any_sync(0xffffffffu, bin);
                    if (ok && (t & 31) == (__ffs(mm) - 1)) atomicAdd(&s_hist[bin], __popc(mm));
                }
                __syncthreads();
                s_suf[t] = s_hist[t];
                __syncthreads();
                for (int st = 1; st < 256; st <<= 1) {
                    int v = s_suf[t] + ((t + st < 256) ? s_suf[t + st] : 0);
                    __syncthreads();
                    s_suf[t] = v;
                    __syncthreads();
                }
                int gt = (t < 255) ? s_suf[t + 1] : 0;
                if (s_suf[t] >= rem && gt < rem) {
                    s_prefix = (pref << 8) | (unsigned)t;
                    s_rem = rem - gt;
                }
                __syncthreads();
            }
            if (t == 0) g_thr[n] = s_prefix;
        }
    }

    // ---- grid barrier 2 ----
    __syncthreads();
    __threadfence();
    if (t == 0) {
        atomicAdd(&g_bar2, 1);
        while (atomicAdd(&g_bar2, 0) < G) __nanosleep(200);
    }
    __syncthreads();

    // ================= Phase C: epilogue (140 units) + final ===============
    if (bx < NN * NBLK) {
        int n   = bx / NBLK;
        int blk = bx % NBLK;
        int i = blk * TPB + t;

        float a1 = 0.f, a2 = 0.f;
        unsigned thr = __ldcg(&g_thr[n]);
        if (i < AA) {
            int id = n * AA + i;
            float con = g_con[id];
            float cn = g_conneg[id];
            int lab = glabel[id];

            if (lab > 0) {
                float sl1 = g_sl1[id];
                float vld = g_validf[id];
                float iou = g_iou[id];
                float w = (vld != 0.f) ? 0.01f * iou : 0.f;
                a1 = sl1 / (sl1 + w) * sl1;
            }
            float nm = (__float_as_uint(cn) >= thr) ? 1.f : 0.f;
            float mm = (lab > 0) ? 1.f : 0.f;
            a2 = con * (mm + nm);
        }

        s_red0[t] = a1; s_red1[t] = a2;
        __syncthreads();
        for (int sd = TPB / 2; sd > 0; sd >>= 1) {
            if (t < sd) { s_red0[t] += s_red0[t + sd]; s_red1[t] += s_red1[t + sd]; }
            __syncthreads();
        }
        if (t == 0) {
            g_part1[n * NBLK + blk] = s_red0[0];
            g_part2[n * NBLK + blk] = s_red1[0];
        }
        __syncthreads();
    }

    // all G blocks arrive; elected last block does deterministic final reduce
    if (t == 0) {
        __threadfence();
        int prev = atomicAdd(&g_done, 1);
        s_last = (prev == G - 1) ? 1 : 0;
    }
    __syncthreads();

    if (s_last) {
        int w = t >> 5, lane = t & 31;
        if (w < NN) {
            float s1 = 0.f, s2 = 0.f;
            for (int b = lane; b < NBLK; b += 32) {
                s1 += g_part1[w * NBLK + b];
                s2 += g_part2[w * NBLK + b];
            }
            float v = s1 + s2;
            #pragma unroll
            for (int o = 16; o > 0; o >>= 1) v += __shfl_down_sync(0xffffffffu, v, o);
            if (lane == 0) {
                int pos = __ldcg(&g_pos[w]);
                s_val[w] = (pos > 0) ? v / fmaxf((float)pos, 1e-6f) : 0.f;
            }
        }
        __syncthreads();
        if (t == 0) {
            out[0] = (s_val[0] + s_val[1] + s_val[2] + s_val[3]) * 0.25f;
            // reset for next graph replay (this block is provably last)
            g_bar1 = 0; g_bar2 = 0; g_done = 0;
            #pragma unroll
            for (int nn = 0; nn < NN; nn++) g_cnt[nn] = 0;
        }
    }
}

// ---------------- launch ----------------
extern "C" void kernel_launch(void* const* d_in, const int* in_sizes, int n_in,
                              void* d_out, int out_size)
{
    const float* ploc   = (const float*)d_in[0];
    const float* plabel = (const float*)d_in[1];
    const float* gloc   = (const float*)d_in[2];
    const int*   glabel = (const int*)d_in[3];
    const float* dbox   = (const float*)d_in[4];
    float* out = (float*)d_out;

    k_all<<<G, TPB>>>(ploc, plabel, gloc, glabel, dbox, out);
}

// round 15
// speedup vs baseline: 1.4882x; 1.2515x over previous
#include <cuda_runtime.h>

#define NN 4
#define AA 8732
#define CC 81
#define TPB 256
#define NBLK ((AA + TPB - 1) / TPB)      /* 35: k_post blocks per batch */

#define APB 128                           /* anchors per k_prep block (2 thr/anchor) */
#define NBLK2 ((AA + APB - 1) / APB)      /* 69 */

#define TPI 256                           /* k_iou threads */
#define JC 128                            /* g-boxes per j-chunk */
#define NJ 69                             /* 69*128 = 8832 >= 8732 */

// ---------------- scratch (device globals: allocation-free) ----------------
__device__ float4 g_pbox[NN * AA];    // (l, t, r, b)
__device__ float4 g_gbox[NN * AA];
__device__ float  g_parea[NN * AA];
__device__ float  g_garea[NN * AA];
__device__ float  g_validf[NN * AA];
__device__ float  g_con[NN * AA];
__device__ float  g_conneg[NN * AA];
__device__ float  g_sl1[NN * AA];
__device__ float  g_ioup[NJ][NN * AA];  // per-chunk IoU partials (positives only)
__device__ int    g_plist[NN * AA];   // compacted positive anchor ids
__device__ int    g_cnt[NN];          // zero-init; reset by k_post each run
__device__ int    g_pos[NN];
__device__ unsigned g_thr[NN];
__device__ float  g_part1[NN * NBLK];
__device__ float  g_part2[NN * NBLK];
__device__ int    g_done;             // zero-init; reset by k_post each run

// ---------------- K1: per-anchor prep (R10 champion, byte-identical) -------
__global__ void __launch_bounds__(TPB) k_prep(
    const float* __restrict__ ploc, const float* __restrict__ plabel,
    const float* __restrict__ gloc, const int* __restrict__ glabel,
    const float* __restrict__ dbox)
{
    int n = blockIdx.y;
    int la = threadIdx.x & (APB - 1);
    int half = threadIdx.x >> 7;          // 0 or 1
    int a = blockIdx.x * APB + la;
    bool act = (a < AA);

    __shared__ float s_se[TPB];
    __shared__ float s_xg[APB];

    int lab = 0;
    float se = 0.f;
    if (act) {
        lab = glabel[n * AA + a];
        const float* pp = plabel + (size_t)n * CC * AA + a;
        int c0 = half ? 41 : 0;
        int c1 = half ? CC : 41;
        #pragma unroll 8
        for (int c = c0; c < c1; c++) se += __expf(pp[(size_t)c * AA]);
        if ((lab >= 41) == (half == 1)) s_xg[la] = pp[(size_t)lab * AA];
    }
    s_se[threadIdx.x] = se;
    __syncthreads();

    if (act && half == 0) {
        float con = __logf(s_se[la] + s_se[la + APB]) - s_xg[la];

        float dx = dbox[0 * AA + a], dy = dbox[1 * AA + a];
        float dw = dbox[2 * AA + a], dh = dbox[3 * AA + a];
        const float* pl = ploc + (size_t)n * 4 * AA;
        const float* gg = gloc + (size_t)n * 4 * AA;
        float px = pl[a], py = pl[AA + a], pw = pl[2 * AA + a], ph = pl[3 * AA + a];
        float gx = gg[a], gy = gg[AA + a], gw = gg[2 * AA + a], gh = gg[3 * AA + a];

        // encode targets (vec_gd) + smooth L1
        float gxt = 10.0f * (gx - dx) / dw;
        float gyt = 10.0f * (gy - dy) / dh;
        float gwt = 5.0f * __logf(gw / dw);
        float ght = 5.0f * __logf(gh / dh);

        float s = 0.f, d, ad;
        d = px - gxt; ad = fabsf(d); s += (ad < 1.f) ? 0.5f * d * d : ad - 0.5f;
        d = py - gyt; ad = fabsf(d); s += (ad < 1.f) ? 0.5f * d * d : ad - 0.5f;
        d = pw - gwt; ad = fabsf(d); s += (ad < 1.f) ? 0.5f * d * d : ad - 0.5f;
        d = ph - ght; ad = fabsf(d); s += (ad < 1.f) ? 0.5f * d * d : ad - 0.5f;

        // decode p -> ltrb
        float pcx = 0.1f * px * dw + dx, pcy = 0.1f * py * dh + dy;
        float pww = __expf(0.2f * pw) * dw, phh = __expf(0.2f * ph) * dh;
        float plx = pcx - 0.5f * pww, pty = pcy - 0.5f * phh;
        float prx = pcx + 0.5f * pww, pby = pcy + 0.5f * phh;
        // decode g -> ltrb
        float gcx = 0.1f * gx * dw + dx, gcy = 0.1f * gy * dh + dy;
        float gww = __expf(0.2f * gw) * dw, ghh = __expf(0.2f * gh) * dh;
        float glx = gcx - 0.5f * gww, gty = gcy - 0.5f * ghh;
        float grx = gcx + 0.5f * gww, gby = gcy + 0.5f * ghh;

        float pa = (prx - plx) * (pby - pty);
        float ga = (grx - glx) * (gby - gty);
        int valid = (plx < prx) && (pty < pby);

        int id = n * AA + a;
        g_pbox[id] = make_float4(plx, pty, prx, pby);
        g_gbox[id] = make_float4(glx, gty, grx, gby);
        g_parea[id] = pa;
        g_garea[id] = ga;
        g_validf[id] = valid ? 1.f : 0.f;
        g_con[id] = con;
        g_conneg[id] = (lab > 0) ? 0.f : con;
        g_sl1[id] = s;

        if (lab > 0) {
            int idx = atomicAdd(&g_cnt[n], 1);
            g_plist[n * AA + idx] = a;
        }
    }
}

// ------- K2: j-chunk IoU partials (276 blocks) + radix select (4 blocks) ---
// grid (NJ+1, NN). bx==NJ: exact K-th largest of conneg bits (R10 champion).
// bx<NJ: load 128-g-box chunk to shared once; thread t sweeps positive
// anchor slot t over the chunk; partial to g_ioup[bx][anchor].
__global__ void __launch_bounds__(TPI) k_iou()
{
    int n = blockIdx.y;
    int bx = blockIdx.x;
    int t = threadIdx.x;

    if (bx == NJ) {
        // ---- radix select on float bits of conneg (R10 champion code) ----
        __shared__ int s_hist[256];
        __shared__ int s_suf[256];
        __shared__ unsigned s_prefix;
        __shared__ int s_rem;
        int pos = g_cnt[n];
        int K = min(3 * pos, AA);
        if (t == 0) { g_pos[n] = pos; s_prefix = 0; s_rem = K; }
        __syncthreads();
        if (K <= 0) { if (t == 0) g_thr[n] = 0xFFFFFFFFu; return; }

        for (int pass = 0; pass < 4; pass++) {
            int shift = 24 - 8 * pass;
            s_hist[t] = 0;
            __syncthreads();
            unsigned pref = s_prefix;
            int rem = s_rem;
            for (int i = t; i < 9216; i += TPI) {
                bool ok = (i < AA);
                unsigned bits = 0;
                if (ok) {
                    bits = __float_as_uint(g_conneg[n * AA + i]);
                    if (pass > 0 && (bits >> (shift + 8)) != pref) ok = false;
                }
                int bin = ok ? (int)((bits >> shift) & 0xFF) : (256 + (t & 31));
                unsigned mm = __match_any_sync(0xffffffffu, bin);
                if (ok && (t & 31) == (__ffs(mm) - 1)) atomicAdd(&s_hist[bin], __popc(mm));
            }
            __syncthreads();
            s_suf[t] = s_hist[t];
            __syncthreads();
            for (int st = 1; st < 256; st <<= 1) {
                int v = s_suf[t] + ((t + st < 256) ? s_suf[t + st] : 0);
                __syncthreads();
                s_suf[t] = v;
                __syncthreads();
            }
            int gt = (t < 255) ? s_suf[t + 1] : 0;
            if (s_suf[t] >= rem && gt < rem) {
                s_prefix = (pref << 8) | (unsigned)t;
                s_rem = rem - gt;
            }
            __syncthreads();
        }
        if (t == 0) g_thr[n] = s_prefix;
        return;
    }

    __shared__ float4 s_gb[JC];
    __shared__ float  s_ga[JC];

    if (t < JC) {
        int j = bx * JC + t;
        if (j < AA) {
            s_gb[t] = g_gbox[n * AA + j];
            s_ga[t] = g_garea[n * AA + j];
        } else {
            s_gb[t] = make_float4(1e30f, 1e30f, 1e30f, 1e30f);
            s_ga[t] = 1.0f;
        }
    }
    __syncthreads();

    int cnt = g_cnt[n];
    for (int slot = t; slot < cnt; slot += TPI) {
        int aid = g_plist[n * AA + slot];
        float4 pb = g_pbox[n * AA + aid];
        float pa = g_parea[n * AA + aid];

        float a0 = 0.f, a1 = 0.f, a2 = 0.f, a3 = 0.f;
        #pragma unroll 8
        for (int u = 0; u < JC; u++) {
            float4 gb = s_gb[u];
            float ga = s_ga[u];
            float x1 = fmaxf(pb.x, gb.x);
            float x2 = fminf(pb.z, gb.z);
            float y1 = fmaxf(pb.y, gb.y);
            float y2 = fminf(pb.w, gb.w);
            float iw = fmaxf(x2 - x1, 0.f);
            float ih = fmaxf(y2 - y1, 0.f);
            float inter = iw * ih;
            float ua = fmaf(inter, -1.0f, pa + ga);
            float r;
            asm("rcp.approx.f32 %0, %1;" : "=f"(r) : "f"(ua));
            float v = inter * r;
            switch (u & 3) {
                case 0: a0 += v; break;
                case 1: a1 += v; break;
                case 2: a2 += v; break;
                default: a3 += v; break;
            }
        }
        g_ioup[bx][n * AA + aid] = (a0 + a1) + (a2 + a3);
    }
}

// ------- K3: epilogue + block reduce + last-block deterministic final ------
__global__ void __launch_bounds__(TPB) k_post(const int* __restrict__ glabel,
                                              float* __restrict__ out)
{
    int n = blockIdx.y;
    int i = blockIdx.x * TPB + threadIdx.x;
    int t = threadIdx.x;

    float a1 = 0.f, a2 = 0.f;
    if (i < AA) {
        int id = n * AA + i;
        float con = g_con[id];
        float cn = g_conneg[id];
        int lab = glabel[id];

        if (lab > 0) {
            float iou = 0.f;
            #pragma unroll
            for (int s = 0; s < NJ; s++) iou += g_ioup[s][id];
            float sl1 = g_sl1[id];
            float vld = g_validf[id];
            float w = (vld != 0.f) ? 0.01f * iou : 0.f;
            a1 = sl1 / (sl1 + w) * sl1;
        }
        float nm = (__float_as_uint(cn) >= g_thr[n]) ? 1.f : 0.f;
        float mm = (lab > 0) ? 1.f : 0.f;
        a2 = con * (mm + nm);
    }

    __shared__ float r1[TPB];
    __shared__ float r2[TPB];
    r1[t] = a1; r2[t] = a2;
    __syncthreads();
    for (int sdim = TPB / 2; sdim > 0; sdim >>= 1) {
        if (t < sdim) { r1[t] += r1[t + sdim]; r2[t] += r2[t + sdim]; }
        __syncthreads();
    }

    __shared__ int s_last;
    if (t == 0) {
        g_part1[n * NBLK + blockIdx.x] = r1[0];
        g_part2[n * NBLK + blockIdx.x] = r2[0];
        __threadfence();
        int prev = atomicAdd(&g_done, 1);
        s_last = (prev == NN * NBLK - 1) ? 1 : 0;
    }
    __syncthreads();

    if (s_last) {
        __shared__ float s_val[NN];
        int w = t >> 5, lane = t & 31;
        if (w < NN) {
            float s1 = 0.f, s2 = 0.f;
            for (int b = lane; b < NBLK; b += 32) {
                s1 += g_part1[w * NBLK + b];
                s2 += g_part2[w * NBLK + b];
            }
            float v = s1 + s2;
            #pragma unroll
            for (int o = 16; o > 0; o >>= 1) v += __shfl_down_sync(0xffffffffu, v, o);
            if (lane == 0) {
                int pos = g_pos[w];
                s_val[w] = (pos > 0) ? v / fmaxf((float)pos, 1e-6f) : 0.f;
            }
        }
        __syncthreads();
        if (t == 0) {
            out[0] = (s_val[0] + s_val[1] + s_val[2] + s_val[3]) * 0.25f;
            g_done = 0;                       // reset for next graph replay
            #pragma unroll
            for (int nn = 0; nn < NN; nn++) g_cnt[nn] = 0;
        }
    }
}

// ---------------- launch ----------------
extern "C" void kernel_launch(void* const* d_in, const int* in_sizes, int n_in,
                              void* d_out, int out_size)
{
    const float* ploc   = (const float*)d_in[0];
    const float* plabel = (const float*)d_in[1];
    const float* gloc   = (const float*)d_in[2];
    const int*   glabel = (const int*)d_in[3];
    const float* dbox   = (const float*)d_in[4];
    float* out = (float*)d_out;

    k_prep<<<dim3(NBLK2, NN), TPB>>>(ploc, plabel, gloc, glabel, dbox);
    k_iou<<<dim3(NJ + 1, NN), TPI>>>();
    k_post<<<dim3(NBLK, NN), TPB>>>(glabel, out);
}